// round 6
// baseline (speedup 1.0000x reference)
#include <cuda_runtime.h>
#include <cuda_bf16.h>
#include <cstdint>

#define NODES 100000
#define EDGES 1600000
#define D 32
#define LAYERS 3
#define HOPS 3

#define SCAN_B 512

// ---------------- scratch (device globals) ----------------
__device__ float g_tmp3[NODES * 3];               // [deg | count | fill] one memset
__device__ unsigned long long g_scanstate[256];   // decoupled-lookback state (memset per call)
__device__ int   g_rowptr[NODES + 1];
__device__ __align__(16) int2 g_epack[EDGES];     // (row, __float_as_int(norm)) grouped by col
__device__ float g_P[4 * NODES * D];              // P_k = x @ W[l,k]
__device__ float g_bufS[NODES * D];
__device__ float g_bufG[NODES * D];
__device__ float g_x[NODES * D];

// ---------------- f32x2 helpers ----------------
__device__ __forceinline__ unsigned long long pack2(float a, float b) {
    unsigned long long r;
    asm("mov.b64 %0, {%1, %2};" : "=l"(r) : "f"(a), "f"(b));
    return r;
}
__device__ __forceinline__ float2 unpack2(unsigned long long v) {
    float2 r;
    asm("mov.b64 {%0, %1}, %2;" : "=f"(r.x), "=f"(r.y) : "l"(v));
    return r;
}
__device__ __forceinline__ void fma2(unsigned long long& d,
                                     unsigned long long a, unsigned long long b) {
    asm("fma.rn.f32x2 %0, %1, %2, %0;" : "+l"(d) : "l"(a), "l"(b));
}

// ---------------- setup kernels ----------------

__global__ void deg_kernel(const int* __restrict__ col, const float* __restrict__ ew, int E)
{
    int e = blockIdx.x * blockDim.x + threadIdx.x;
    if (e < E) {
        int c = col[e];
        atomicAdd(&g_tmp3[c], ew[e]);                                  // deg (raw)
        atomicAdd(reinterpret_cast<int*>(g_tmp3 + NODES) + c, 1);      // count
    }
}

// single-pass exclusive scan of count -> rowptr, decoupled lookback across blocks
__global__ void scanfused_kernel(int N, int E)
{
    __shared__ int sh[SCAN_B];
    __shared__ int s_prefix;
    const int* cnt = reinterpret_cast<const int*>(g_tmp3 + NODES);
    int t = threadIdx.x, b = blockIdx.x;
    int i = b * SCAN_B + t;
    int v = (i < N) ? cnt[i] : 0;
    sh[t] = v;
    __syncthreads();
#pragma unroll
    for (int off = 1; off < SCAN_B; off <<= 1) {
        int add = (t >= off) ? sh[t - off] : 0;
        __syncthreads();
        sh[t] += add;
        __syncthreads();
    }
    int incl = sh[t];
    int total = sh[SCAN_B - 1];

    if (t == 0) {
        // post aggregate (flag 1) or inclusive (flag 2 for block 0)
        unsigned long long flag = (b == 0) ? 2ull : 1ull;
        atomicExch(&g_scanstate[b], (flag << 32) | (unsigned)total);
        int prefix = 0;
        if (b > 0) {
            int j = b - 1;
            while (true) {
                unsigned long long s;
                do { s = atomicAdd(&g_scanstate[j], 0ull); } while ((s >> 32) == 0ull);
                prefix += (int)(unsigned)s;
                if ((s >> 32) == 2ull) break;
                j--;
            }
            atomicExch(&g_scanstate[b], (2ull << 32) | (unsigned)(prefix + total));
        }
        s_prefix = prefix;
    }
    __syncthreads();
    if (i < N) g_rowptr[i] = s_prefix + incl - v;
    if (i == N) g_rowptr[N] = E;
}

// scatter edges into CSR slots grouped by col; norm computed inline from raw deg
__global__ void fill_kernel(const int* __restrict__ row, const int* __restrict__ col,
                            const float* __restrict__ ew, int E)
{
    int* fill = reinterpret_cast<int*>(g_tmp3 + 2 * NODES);
    int e = blockIdx.x * blockDim.x + threadIdx.x;
    if (e < E) {
        int r = row[e];
        int c = col[e];
        float dr = g_tmp3[r];
        float dc = g_tmp3[c];
        float sr = (dr > 0.0f) ? rsqrtf(dr) : 0.0f;
        float sc = (dc > 0.0f) ? rsqrtf(dc) : 0.0f;
        float w = sr * ew[e] * sc;
        int p = g_rowptr[c] + atomicAdd(&fill[c], 1);
        g_epack[p] = make_int2(r, __float_as_int(w));
    }
}

// ---------------- multigemm: P[k][n,:] = x[n,:] @ W4[k]  for k=0..3 ----------------
__global__ __launch_bounds__(256)
void multigemm_kernel(float* __restrict__ P, const float* __restrict__ x,
                      const float* __restrict__ W4, int N)
{
    __shared__ float Ws[4 * D * D];   // 16 KB
    int t = threadIdx.x;
#pragma unroll
    for (int q = 0; q < 4; q++)
        reinterpret_cast<float4*>(Ws)[q * 256 + t] =
            reinterpret_cast<const float4*>(W4)[q * 256 + t];
    __syncthreads();

    int n = blockIdx.x * 256 + t;
    if (n >= N) return;

    float h[D];
    const float4* xr = reinterpret_cast<const float4*>(x + (size_t)n * D);
#pragma unroll
    for (int q = 0; q < 8; q++) {
        float4 v = xr[q];
        h[q * 4] = v.x; h[q * 4 + 1] = v.y; h[q * 4 + 2] = v.z; h[q * 4 + 3] = v.w;
    }

#pragma unroll
    for (int k = 0; k < 4; k++) {
        unsigned long long acc[D / 2];
#pragma unroll
        for (int j = 0; j < D / 2; j++) acc[j] = 0ull;

        const unsigned long long* Wk =
            reinterpret_cast<const unsigned long long*>(Ws + k * D * D);
#pragma unroll
        for (int i = 0; i < D; i++) {
            unsigned long long hv2 = pack2(h[i], h[i]);
            const unsigned long long* wr = Wk + i * (D / 2);
#pragma unroll
            for (int j = 0; j < D / 2; j++)
                fma2(acc[j], hv2, wr[j]);
        }

        float* drow = P + (size_t)k * N * D + (size_t)n * D;
#pragma unroll
        for (int j2 = 0; j2 < D / 4; j2++) {
            float2 a = unpack2(acc[j2 * 2]);
            float2 b = unpack2(acc[j2 * 2 + 1]);
            reinterpret_cast<float4*>(drow)[j2] = make_float4(a.x, a.y, b.x, b.y);
        }
    }
}

// ---------------- fused hop: dst[n,:] = P[n,:] + sum_e norm_e * h[row_e,:]
// mode 0: plain;  mode 1: + bias then ReLU
__global__ void gather_kernel(float* __restrict__ dst, const float* __restrict__ h,
                              const float* __restrict__ P, const float* __restrict__ bias,
                              int mode, int N)
{
    int gt = blockIdx.x * blockDim.x + threadIdx.x;
    int n = gt >> 5;
    int lane = gt & 31;
    if (n >= N) return;

    int s = g_rowptr[n];
    int e = g_rowptr[n + 1];
    float acc = 0.0f;

    int i = s;
    if ((i & 1) && i < e) {
        int2 t = g_epack[i];
        acc = fmaf(__int_as_float(t.y), __ldg(h + (size_t)t.x * D + lane), acc);
        i++;
    }
    int npair = (e - i) >> 1;
    const int4* pp = reinterpret_cast<const int4*>(g_epack + i);
#pragma unroll 4
    for (int p = 0; p < npair; p++) {
        int4 t = pp[p];
        float v0 = __ldg(h + (size_t)t.x * D + lane);
        float v1 = __ldg(h + (size_t)t.z * D + lane);
        acc = fmaf(__int_as_float(t.y), v0, acc);
        acc = fmaf(__int_as_float(t.w), v1, acc);
    }
    i += npair * 2;
    if (i < e) {
        int2 t = g_epack[i];
        acc = fmaf(__int_as_float(t.y), __ldg(h + (size_t)t.x * D + lane), acc);
    }

    float v = P[(size_t)n * D + lane] + acc;
    if (mode == 1) v = fmaxf(v + bias[lane], 0.0f);
    dst[(size_t)n * D + lane] = v;
}

// ---------------- launch ----------------

extern "C" void kernel_launch(void* const* d_in, const int* in_sizes, int n_in,
                              void* d_out, int out_size)
{
    const float* x  = (const float*)d_in[0];
    const int*   ei = (const int*)d_in[1];
    const float* ew = (const float*)d_in[2];
    const float* W  = (const float*)d_in[3];
    const float* b  = (const float*)d_in[4];

    const int N = in_sizes[0] / D;
    const int E = in_sizes[2];

    const int* row = ei;
    const int* col = ei + E;

    float* tmp3_p;  cudaGetSymbolAddress((void**)&tmp3_p,  g_tmp3);
    void*  scan_p;  cudaGetSymbolAddress(&scan_p,          g_scanstate);
    float* P_p;     cudaGetSymbolAddress((void**)&P_p,     g_P);
    float* bufS_p;  cudaGetSymbolAddress((void**)&bufS_p,  g_bufS);
    float* bufG_p;  cudaGetSymbolAddress((void**)&bufG_p,  g_bufG);
    float* x_p;     cudaGetSymbolAddress((void**)&x_p,     g_x);

    const int TB = 256;
    const int eb = (E + TB - 1) / TB;
    const int scan_blocks = (N + SCAN_B - 1) / SCAN_B;

    // ---- CSR + norm build ----
    cudaMemsetAsync(tmp3_p, 0, (size_t)3 * N * sizeof(float));
    cudaMemsetAsync(scan_p, 0, 256 * sizeof(unsigned long long));
    deg_kernel<<<eb, TB>>>(col, ew, E);
    scanfused_kernel<<<scan_blocks, SCAN_B>>>(N, E);
    fill_kernel<<<eb, TB>>>(row, col, ew, E);

    const int mg_blocks     = (N + 255) / 256;
    const int gather_blocks = (N * 32 + TB - 1) / TB;
    const size_t ND = (size_t)N * D;

    const float* xcur = x;
    for (int l = 0; l < LAYERS; l++) {
        const float* Wl = W + (size_t)l * (HOPS + 1) * D * D;
        multigemm_kernel<<<mg_blocks, 256>>>(P_p, xcur, Wl, N);

        // Horner: x' = relu(P0 + A(P1 + A(P2 + A*P3)) + b)
        gather_kernel<<<gather_blocks, TB>>>(bufS_p, P_p + 3 * ND, P_p + 2 * ND,
                                             nullptr, 0, N);
        gather_kernel<<<gather_blocks, TB>>>(bufG_p, bufS_p, P_p + 1 * ND,
                                             nullptr, 0, N);
        float* dst = (l == LAYERS - 1) ? (float*)d_out : x_p;
        gather_kernel<<<gather_blocks, TB>>>(dst, bufG_p, P_p,
                                             b + (size_t)l * D, 1, N);
        xcur = x_p;
    }
}

// round 8
// speedup vs baseline: 1.0008x; 1.0008x over previous
#include <cuda_runtime.h>
#include <cuda_bf16.h>
#include <cstdint>

#define NODES 100000
#define EDGES 1600000
#define D 32
#define LAYERS 3
#define HOPS 3

#define SCAN_B 512

// ---------------- scratch (device globals) ----------------
__device__ float g_tmp3[NODES * 3];               // [deg | count | fill] one memset
__device__ unsigned long long g_scanstate[256];   // decoupled-lookback state
__device__ int   g_rowptr[NODES + 1];
__device__ __align__(16) int2 g_epack[EDGES];     // (row, __float_as_int(norm)) grouped by col
__device__ float g_P[4 * NODES * D];              // P_k = x @ W[l,k]
__device__ float g_bufS[NODES * D];
__device__ float g_bufG[NODES * D];
__device__ float g_x[NODES * D];

// ---------------- f32x2 helpers ----------------
__device__ __forceinline__ unsigned long long pack2(float a, float b) {
    unsigned long long r;
    asm("mov.b64 %0, {%1, %2};" : "=l"(r) : "f"(a), "f"(b));
    return r;
}
__device__ __forceinline__ float2 unpack2(unsigned long long v) {
    float2 r;
    asm("mov.b64 {%0, %1}, %2;" : "=f"(r.x), "=f"(r.y) : "l"(v));
    return r;
}
__device__ __forceinline__ void fma2(unsigned long long& d,
                                     unsigned long long a, unsigned long long b) {
    asm("fma.rn.f32x2 %0, %1, %2, %0;" : "+l"(d) : "l"(a), "l"(b));
}

// ---------------- setup kernels ----------------

__global__ void deg_kernel(const int* __restrict__ col, const float* __restrict__ ew, int E)
{
    int e = blockIdx.x * blockDim.x + threadIdx.x;
    if (e < E) {
        int c = col[e];
        atomicAdd(&g_tmp3[c], ew[e]);                                  // deg (raw)
        atomicAdd(reinterpret_cast<int*>(g_tmp3 + NODES) + c, 1);      // count
    }
}

// single-pass exclusive scan of count -> rowptr, decoupled lookback across blocks
__global__ void scanfused_kernel(int N, int E)
{
    __shared__ int sh[SCAN_B];
    __shared__ int s_prefix;
    const int* cnt = reinterpret_cast<const int*>(g_tmp3 + NODES);
    int t = threadIdx.x, b = blockIdx.x;
    int i = b * SCAN_B + t;
    int v = (i < N) ? cnt[i] : 0;
    sh[t] = v;
    __syncthreads();
#pragma unroll
    for (int off = 1; off < SCAN_B; off <<= 1) {
        int add = (t >= off) ? sh[t - off] : 0;
        __syncthreads();
        sh[t] += add;
        __syncthreads();
    }
    int incl = sh[t];
    int total = sh[SCAN_B - 1];

    if (t == 0) {
        unsigned long long flag = (b == 0) ? 2ull : 1ull;
        atomicExch(&g_scanstate[b], (flag << 32) | (unsigned)total);
        int prefix = 0;
        if (b > 0) {
            int j = b - 1;
            while (true) {
                unsigned long long s;
                do { s = atomicAdd(&g_scanstate[j], 0ull); } while ((s >> 32) == 0ull);
                prefix += (int)(unsigned)s;
                if ((s >> 32) == 2ull) break;
                j--;
            }
            atomicExch(&g_scanstate[b], (2ull << 32) | (unsigned)(prefix + total));
        }
        s_prefix = prefix;
    }
    __syncthreads();
    if (i < N) g_rowptr[i] = s_prefix + incl - v;
    if (i == N) g_rowptr[N] = E;
}

// scatter edges into CSR slots grouped by col; norm computed inline from raw deg
__global__ void fill_kernel(const int* __restrict__ row, const int* __restrict__ col,
                            const float* __restrict__ ew, int E)
{
    int* fill = reinterpret_cast<int*>(g_tmp3 + 2 * NODES);
    int e = blockIdx.x * blockDim.x + threadIdx.x;
    if (e < E) {
        int r = row[e];
        int c = col[e];
        float dr = g_tmp3[r];
        float dc = g_tmp3[c];
        float sr = (dr > 0.0f) ? rsqrtf(dr) : 0.0f;
        float sc = (dc > 0.0f) ? rsqrtf(dc) : 0.0f;
        float w = sr * ew[e] * sc;
        int p = g_rowptr[c] + atomicAdd(&fill[c], 1);
        g_epack[p] = make_int2(r, __float_as_int(w));
    }
}

// ---------------- multigemm: P[k][n,:] = x[n,:] @ W4[k]  for k=0..3 ----------------
// 2 nodes per thread; W row broadcast via LDS.128; 1:8 LDS:FFMA2 ratio.
__global__ __launch_bounds__(256, 1)
void multigemm_kernel(float* __restrict__ P, const float* __restrict__ x,
                      const float* __restrict__ W4, int N)
{
    __shared__ __align__(16) float Ws[4 * D * D];   // 16 KB
    int t = threadIdx.x;
#pragma unroll
    for (int q = 0; q < 4; q++)
        reinterpret_cast<float4*>(Ws)[q * 256 + t] =
            reinterpret_cast<const float4*>(W4)[q * 256 + t];
    __syncthreads();

    int n0 = blockIdx.x * 512 + t;
    int n1 = n0 + 256;
    bool v0 = n0 < N, v1 = n1 < N;

    float h0[D], h1[D];
    const float4* x0 = reinterpret_cast<const float4*>(x + (size_t)n0 * D);
    const float4* x1 = reinterpret_cast<const float4*>(x + (size_t)n1 * D);
#pragma unroll
    for (int q = 0; q < 8; q++) {
        float4 a = v0 ? __ldg(x0 + q) : make_float4(0, 0, 0, 0);
        h0[q*4] = a.x; h0[q*4+1] = a.y; h0[q*4+2] = a.z; h0[q*4+3] = a.w;
        float4 c = v1 ? __ldg(x1 + q) : make_float4(0, 0, 0, 0);
        h1[q*4] = c.x; h1[q*4+1] = c.y; h1[q*4+2] = c.z; h1[q*4+3] = c.w;
    }

#pragma unroll
    for (int k = 0; k < 4; k++) {
        unsigned long long acc0[D / 2], acc1[D / 2];
#pragma unroll
        for (int j = 0; j < D / 2; j++) { acc0[j] = 0ull; acc1[j] = 0ull; }

        const ulonglong2* Wk = reinterpret_cast<const ulonglong2*>(Ws + k * D * D);
#pragma unroll
        for (int i = 0; i < D; i++) {
            unsigned long long hv0 = pack2(h0[i], h0[i]);
            unsigned long long hv1 = pack2(h1[i], h1[i]);
            const ulonglong2* wr = Wk + i * 8;   // 8 ulonglong2 = 32 floats
#pragma unroll
            for (int j = 0; j < 8; j++) {
                ulonglong2 w = wr[j];
                fma2(acc0[j*2],     hv0, w.x);
                fma2(acc0[j*2 + 1], hv0, w.y);
                fma2(acc1[j*2],     hv1, w.x);
                fma2(acc1[j*2 + 1], hv1, w.y);
            }
        }

        float* d0 = P + (size_t)k * N * D + (size_t)n0 * D;
        float* d1 = P + (size_t)k * N * D + (size_t)n1 * D;
#pragma unroll
        for (int j2 = 0; j2 < D / 4; j2++) {
            if (v0) {
                float2 a = unpack2(acc0[j2*2]);
                float2 b = unpack2(acc0[j2*2 + 1]);
                reinterpret_cast<float4*>(d0)[j2] = make_float4(a.x, a.y, b.x, b.y);
            }
            if (v1) {
                float2 a = unpack2(acc1[j2*2]);
                float2 b = unpack2(acc1[j2*2 + 1]);
                reinterpret_cast<float4*>(d1)[j2] = make_float4(a.x, a.y, b.x, b.y);
            }
        }
    }
}

// ---------------- fused hop: dst[n,:] = P[n,:] + sum_e norm_e * h[row_e,:]
// mode 0: plain;  mode 1: + bias then ReLU
__global__ void gather_kernel(float* __restrict__ dst, const float* __restrict__ h,
                              const float* __restrict__ P, const float* __restrict__ bias,
                              int mode, int N)
{
    int gt = blockIdx.x * blockDim.x + threadIdx.x;
    int n = gt >> 5;
    int lane = gt & 31;
    if (n >= N) return;

    int s = g_rowptr[n];
    int e = g_rowptr[n + 1];
    float acc0 = 0.0f, acc1 = 0.0f;

    int i = s;
    if ((i & 1) && i < e) {
        int2 t = g_epack[i];
        acc0 = fmaf(__int_as_float(t.y), __ldg(h + (size_t)t.x * D + lane), acc0);
        i++;
    }
    int npair = (e - i) >> 1;
    const int4* pp = reinterpret_cast<const int4*>(g_epack + i);
#pragma unroll 4
    for (int p = 0; p < npair; p++) {
        int4 t = pp[p];
        float v0 = __ldg(h + (size_t)t.x * D + lane);
        float v1 = __ldg(h + (size_t)t.z * D + lane);
        acc0 = fmaf(__int_as_float(t.y), v0, acc0);
        acc1 = fmaf(__int_as_float(t.w), v1, acc1);
    }
    i += npair * 2;
    if (i < e) {
        int2 t = g_epack[i];
        acc0 = fmaf(__int_as_float(t.y), __ldg(h + (size_t)t.x * D + lane), acc0);
    }

    float v = P[(size_t)n * D + lane] + acc0 + acc1;
    if (mode == 1) v = fmaxf(v + bias[lane], 0.0f);
    dst[(size_t)n * D + lane] = v;
}

// ---------------- launch ----------------

extern "C" void kernel_launch(void* const* d_in, const int* in_sizes, int n_in,
                              void* d_out, int out_size)
{
    const float* x  = (const float*)d_in[0];
    const int*   ei = (const int*)d_in[1];
    const float* ew = (const float*)d_in[2];
    const float* W  = (const float*)d_in[3];
    const float* b  = (const float*)d_in[4];

    const int N = in_sizes[0] / D;
    const int E = in_sizes[2];

    const int* row = ei;
    const int* col = ei + E;

    float* tmp3_p;  cudaGetSymbolAddress((void**)&tmp3_p,  g_tmp3);
    void*  scan_p;  cudaGetSymbolAddress(&scan_p,          g_scanstate);
    float* P_p;     cudaGetSymbolAddress((void**)&P_p,     g_P);
    float* bufS_p;  cudaGetSymbolAddress((void**)&bufS_p,  g_bufS);
    float* bufG_p;  cudaGetSymbolAddress((void**)&bufG_p,  g_bufG);
    float* x_p;     cudaGetSymbolAddress((void**)&x_p,     g_x);

    const int TB = 256;
    const int eb = (E + TB - 1) / TB;
    const int scan_blocks = (N + SCAN_B - 1) / SCAN_B;

    // ---- CSR + norm build ----
    cudaMemsetAsync(tmp3_p, 0, (size_t)3 * N * sizeof(float));
    cudaMemsetAsync(scan_p, 0, 256 * sizeof(unsigned long long));
    deg_kernel<<<eb, TB>>>(col, ew, E);
    scanfused_kernel<<<scan_blocks, SCAN_B>>>(N, E);
    fill_kernel<<<eb, TB>>>(row, col, ew, E);

    const int mg_blocks     = (N + 511) / 512;
    const int gather_blocks = (N * 32 + TB - 1) / TB;
    const size_t ND = (size_t)N * D;

    const float* xcur = x;
    for (int l = 0; l < LAYERS; l++) {
        const float* Wl = W + (size_t)l * (HOPS + 1) * D * D;
        multigemm_kernel<<<mg_blocks, 256>>>(P_p, xcur, Wl, N);

        // Horner: x' = relu(P0 + A(P1 + A(P2 + A*P3)) + b)
        gather_kernel<<<gather_blocks, TB>>>(bufS_p, P_p + 3 * ND, P_p + 2 * ND,
                                             nullptr, 0, N);
        gather_kernel<<<gather_blocks, TB>>>(bufG_p, bufS_p, P_p + 1 * ND,
                                             nullptr, 0, N);
        float* dst = (l == LAYERS - 1) ? (float*)d_out : x_p;
        gather_kernel<<<gather_blocks, TB>>>(dst, bufG_p, P_p,
                                             b + (size_t)l * D, 1, N);
        xcur = x_p;
    }
}